// round 6
// baseline (speedup 1.0000x reference)
#include <cuda_runtime.h>
#include <cstdint>

// Problem constants
#define BB  2
#define HH  16
#define SS  2048
#define DD  64
#define BHN (BB*HH)

#define TM  128          // q rows per CTA
#define TN  128          // keys per tile
#define NT  (SS/TN)      // 16 key tiles
#define PQ  68           // smem pitch for Q/K tiles (words)
#define PW  132          // smem pitch for W tile (words, mult of 4 for float4 STS)
#define PV  130          // smem pitch for transposed V tile (words)
#define SCL 0.125f       // 1/sqrt(64)

typedef unsigned long long ull;

// Row-wise 1/sum(exp) scratch: 32*2048 floats = 256 KB static device global.
__device__ float g_invZ[BHN * SS];

// Packed f32x2 FMA (sm_100+): acc.{lo,hi} += a.{lo,hi} * b.{lo,hi}
__device__ __forceinline__ void fma2(ull& acc, ull a, ull b) {
    asm("fma.rn.f32x2 %0, %1, %2, %0;" : "+l"(acc) : "l"(a), "l"(b));
}
__device__ __forceinline__ float hsum2(ull a) {
    return __uint_as_float((unsigned)a) + __uint_as_float((unsigned)(a >> 32));
}

// ---------------------------------------------------------------------------
// Pass 1: e = exp(QK^T/8 + mask*-1e9) written (unnormalized) to weights buf,
//         plus exact per-row sums -> g_invZ.
// Grid: (BH, S/TM). CTA covers 128 q rows x all 2048 keys for one (b,h).
// ---------------------------------------------------------------------------
__global__ void __launch_bounds__(256, 1)
qk_exp_kernel(const float* __restrict__ q, const float* __restrict__ k,
              const float* __restrict__ mask, float* __restrict__ wts) {
    extern __shared__ float sm[];
    float* Qs = sm;                    // [TM][PQ]
    float* Ks = sm + TM * PQ;          // [TN][PQ]
    float* zr = sm + 2 * TM * PQ;      // [TM][16]

    const int tid = threadIdx.x;
    const int ty  = tid >> 4;          // 0..15  -> rows ty*8..ty*8+7
    const int tx  = tid & 15;          // 0..15  -> cols c*16+tx
    const int bh  = blockIdx.x;
    const int qb  = blockIdx.y;
    const int b   = bh / HH;

    const float* qp = q    + ((size_t)bh * SS + (size_t)qb * TM) * DD;
    const float* kp = k    + (size_t)bh * SS * DD;
    const float* mp = mask + ((size_t)b  * SS + (size_t)qb * TM) * SS;
    float*       wp = wts  + ((size_t)bh * SS + (size_t)qb * TM) * SS;

    // Load Q tile [128][64] (coalesced float4)
    #pragma unroll
    for (int it = 0; it < 8; it++) {
        int lin = it * 256 + tid;
        int row = lin >> 4;
        int c4  = (lin & 15) << 2;
        *(float4*)(Qs + row * PQ + c4) = *(const float4*)(qp + (size_t)row * DD + c4);
    }

    float zp[8];
    #pragma unroll
    for (int r = 0; r < 8; r++) zp[r] = 0.f;

    for (int t = 0; t < NT; t++) {
        __syncthreads();   // protect Ks (and Qs on t==0)
        #pragma unroll
        for (int it = 0; it < 8; it++) {
            int lin = it * 256 + tid;
            int row = lin >> 4;
            int c4  = (lin & 15) << 2;
            *(float4*)(Ks + row * PQ + c4) =
                *(const float4*)(kp + (size_t)(t * TN + row) * DD + c4);
        }
        __syncthreads();

        // 128x128 logits tile, 8x8 per thread, f32x2 paired along D
        ull acc[8][8];
        #pragma unroll
        for (int r = 0; r < 8; r++)
            #pragma unroll
            for (int c = 0; c < 8; c++) acc[r][c] = 0ull;

        #pragma unroll 2
        for (int d = 0; d < DD; d += 2) {
            ull a2[8], b2[8];
            #pragma unroll
            for (int r = 0; r < 8; r++)
                a2[r] = *(const ull*)(Qs + (ty * 8 + r) * PQ + d);
            #pragma unroll
            for (int c = 0; c < 8; c++)
                b2[c] = *(const ull*)(Ks + (c * 16 + tx) * PQ + d);
            #pragma unroll
            for (int r = 0; r < 8; r++)
                #pragma unroll
                for (int c = 0; c < 8; c++)
                    fma2(acc[r][c], a2[r], b2[c]);
        }

        // Epilogue: mask, exp, store unnormalized e, accumulate row sums
        #pragma unroll
        for (int r = 0; r < 8; r++) {
            const int row = ty * 8 + r;
            const float* mrow = mp + (size_t)row * SS + (size_t)t * TN;
            float*       wrow = wp + (size_t)row * SS + (size_t)t * TN;
            float zs = 0.f;
            #pragma unroll
            for (int c = 0; c < 8; c++) {
                int col = c * 16 + tx;
                float dot = hsum2(acc[r][c]) * SCL;
                float e = __expf(fmaf(mrow[col], -1e9f, dot)); // masked -> exp()=0
                wrow[col] = e;
                zs += e;
            }
            zp[r] += zs;
        }
    }

    // Row-sum reduction across the 16 tx threads per row
    #pragma unroll
    for (int r = 0; r < 8; r++) zr[(ty * 8 + r) * 16 + tx] = zp[r];
    __syncthreads();
    if (tid < TM) {
        float z = 0.f;
        #pragma unroll
        for (int i = 0; i < 16; i++) z += zr[tid * 16 + i];
        g_invZ[(size_t)bh * SS + (size_t)qb * TM + tid] = 1.0f / z;
    }
}

// ---------------------------------------------------------------------------
// Pass 2: read e, scale by 1/Z, write normalized weights back IN PLACE,
//         and accumulate out = W @ V from the smem-staged scaled tile.
// Grid: (BH, S/TM).
// ---------------------------------------------------------------------------
__global__ void __launch_bounds__(256, 1)
pv_kernel(const float* __restrict__ v, float* __restrict__ wts,
          float* __restrict__ out) {
    extern __shared__ float sm[];
    float* Ws = sm;                    // [TM][PW]
    float* Vt = sm + TM * PW;          // [DD][PV]  (transposed V tile)
    float* iZ = Vt + DD * PV;          // [TM]

    const int tid = threadIdx.x;
    const int ty  = tid >> 4;          // rows ty*8..ty*8+7
    const int tx  = tid & 15;          // out cols c*16+tx (c=0..3)
    const int bh  = blockIdx.x;
    const int qb  = blockIdx.y;

    const float* vp = v   + (size_t)bh * SS * DD;
    float*       wp = wts + ((size_t)bh * SS + (size_t)qb * TM) * SS;
    float*       op = out + ((size_t)bh * SS + (size_t)qb * TM) * DD;

    if (tid < TM) iZ[tid] = g_invZ[(size_t)bh * SS + (size_t)qb * TM + tid];

    ull acc[8][4];
    #pragma unroll
    for (int r = 0; r < 8; r++)
        #pragma unroll
        for (int c = 0; c < 4; c++) acc[r][c] = 0ull;

    for (int t = 0; t < NT; t++) {
        __syncthreads();   // protects Ws/Vt (and iZ on t==0)

        // W tile: load e, normalize, write back in place, stash in smem
        #pragma unroll
        for (int it = 0; it < 16; it++) {
            int lin = it * 256 + tid;
            int row = lin >> 5;
            int c4  = (lin & 31) << 2;
            float4 e = *(const float4*)(wp + (size_t)row * SS + (size_t)t * TN + c4);
            float s = iZ[row];
            e.x *= s; e.y *= s; e.z *= s; e.w *= s;
            *(float4*)(wp + (size_t)row * SS + (size_t)t * TN + c4) = e;
            *(float4*)(Ws + row * PW + c4) = e;
        }
        // V tile transposed: Vt[d][j]
        #pragma unroll
        for (int it = 0; it < 8; it++) {
            int lin = it * 256 + tid;
            int row = lin >> 4;
            int d4  = (lin & 15) << 2;
            float4 vv = *(const float4*)(vp + (size_t)(t * TN + row) * DD + d4);
            Vt[(d4 + 0) * PV + row] = vv.x;
            Vt[(d4 + 1) * PV + row] = vv.y;
            Vt[(d4 + 2) * PV + row] = vv.z;
            Vt[(d4 + 3) * PV + row] = vv.w;
        }
        __syncthreads();

        // out[128][64] += Ws[128][128] @ V[128][64]; f32x2 paired along j
        #pragma unroll 2
        for (int j = 0; j < TN; j += 2) {
            ull a2[8], b2[4];
            #pragma unroll
            for (int r = 0; r < 8; r++)
                a2[r] = *(const ull*)(Ws + (ty * 8 + r) * PW + j);
            #pragma unroll
            for (int c = 0; c < 4; c++)
                b2[c] = *(const ull*)(Vt + (c * 16 + tx) * PV + j);
            #pragma unroll
            for (int r = 0; r < 8; r++)
                #pragma unroll
                for (int c = 0; c < 4; c++)
                    fma2(acc[r][c], a2[r], b2[c]);
        }
    }

    #pragma unroll
    for (int r = 0; r < 8; r++)
        #pragma unroll
        for (int c = 0; c < 4; c++)
            op[(size_t)(ty * 8 + r) * DD + c * 16 + tx] = hsum2(acc[r][c]);
}

// ---------------------------------------------------------------------------
extern "C" void kernel_launch(void* const* d_in, const int* in_sizes, int n_in,
                              void* d_out, int out_size) {
    (void)in_sizes; (void)n_in; (void)out_size;
    const float* q    = (const float*)d_in[0];
    const float* k    = (const float*)d_in[1];
    const float* v    = (const float*)d_in[2];
    const float* mask = (const float*)d_in[3];

    float* out = (float*)d_out;                         // [B,H,S,D]
    float* wts = out + (size_t)BB * HH * SS * DD;       // [B,H,S,S]

    const int smem1 = (2 * TM * PQ + TM * 16) * (int)sizeof(float); // 77,824 B
    const int smem2 = (TM * PW + DD * PV + TM) * (int)sizeof(float); // 101,376 B
    cudaFuncSetAttribute(qk_exp_kernel, cudaFuncAttributeMaxDynamicSharedMemorySize, smem1);
    cudaFuncSetAttribute(pv_kernel,     cudaFuncAttributeMaxDynamicSharedMemorySize, smem2);

    dim3 grid(BHN, SS / TM);   // heads fastest -> mask slice stays L2-resident
    qk_exp_kernel<<<grid, 256, smem1>>>(q, k, mask, wts);
    pv_kernel<<<grid, 256, smem2>>>(v, wts, out);
}

// round 9
// speedup vs baseline: 3.3643x; 3.3643x over previous
#include <cuda_runtime.h>
#include <cuda_bf16.h>
#include <cstdint>

#define BB  2
#define HH  16
#define SS  2048
#define DD  64
#define BHN (BB*HH)
#define TM  128
#define TN  128
#define NT  (SS/TN)
#define SCL 0.125f
#define PK  72     // Q/K/V smem pitch in bf16 elems (144 B rows -> conflict-free ldmatrix)
#define PW  136    // W smem pitch in bf16 elems (272 B rows)

typedef unsigned long long ull;

// Per-row 1/sum(exp): static device global (allocation-guard safe)
__device__ float g_invZ[BHN * SS];

// ---------------------------------------------------------------------------
__device__ __forceinline__ uint32_t s2u(const void* p) {
    uint32_t a;
    asm("{ .reg .u64 t; cvta.to.shared.u64 t, %1; cvt.u32.u64 %0, t; }" : "=r"(a) : "l"(p));
    return a;
}

__device__ __forceinline__ void ldsm_x4(uint32_t r[4], uint32_t addr) {
    asm volatile("ldmatrix.sync.aligned.m8n8.x4.shared.b16 {%0,%1,%2,%3}, [%4];"
                 : "=r"(r[0]), "=r"(r[1]), "=r"(r[2]), "=r"(r[3]) : "r"(addr));
}
__device__ __forceinline__ void ldsm_x4t(uint32_t r[4], uint32_t addr) {
    asm volatile("ldmatrix.sync.aligned.m8n8.x4.trans.shared.b16 {%0,%1,%2,%3}, [%4];"
                 : "=r"(r[0]), "=r"(r[1]), "=r"(r[2]), "=r"(r[3]) : "r"(addr));
}
__device__ __forceinline__ void mma16816(float c[4], const uint32_t a[4], const uint32_t* b) {
    asm volatile(
        "mma.sync.aligned.m16n8k16.row.col.f32.bf16.bf16.f32 "
        "{%0,%1,%2,%3}, {%4,%5,%6,%7}, {%8,%9}, {%0,%1,%2,%3};"
        : "+f"(c[0]), "+f"(c[1]), "+f"(c[2]), "+f"(c[3])
        : "r"(a[0]), "r"(a[1]), "r"(a[2]), "r"(a[3]), "r"(b[0]), "r"(b[1]));
}

// fp32x4 -> bf16 hi/lo split, packed 4x u16 per ull
__device__ __forceinline__ void hilo4(float4 f, ull& hp, ull& lp) {
    __nv_bfloat16 h0 = __float2bfloat16(f.x), h1 = __float2bfloat16(f.y);
    __nv_bfloat16 h2 = __float2bfloat16(f.z), h3 = __float2bfloat16(f.w);
    __nv_bfloat16 l0 = __float2bfloat16(f.x - __bfloat162float(h0));
    __nv_bfloat16 l1 = __float2bfloat16(f.y - __bfloat162float(h1));
    __nv_bfloat16 l2 = __float2bfloat16(f.z - __bfloat162float(h2));
    __nv_bfloat16 l3 = __float2bfloat16(f.w - __bfloat162float(h3));
    hp = (ull)__bfloat16_as_ushort(h0) | ((ull)__bfloat16_as_ushort(h1) << 16)
       | ((ull)__bfloat16_as_ushort(h2) << 32) | ((ull)__bfloat16_as_ushort(h3) << 48);
    lp = (ull)__bfloat16_as_ushort(l0) | ((ull)__bfloat16_as_ushort(l1) << 16)
       | ((ull)__bfloat16_as_ushort(l2) << 32) | ((ull)__bfloat16_as_ushort(l3) << 48);
}

// ---------------------------------------------------------------------------
// Pass 1: e = exp(QK^T/8 + mask*-1e9) (unnormalized) -> wts; row sums -> g_invZ
// bf16 3-term split GEMM via mma.sync m16n8k16.
// smem: Qhi/Qlo/Khi/Klo, each [128][PK] bf16.
// ---------------------------------------------------------------------------
#define O1_QHI 0
#define O1_QLO (O1_QHI + TM*PK*2)
#define O1_KHI (O1_QLO + TM*PK*2)
#define O1_KLO (O1_KHI + TM*PK*2)
#define SMEM1  (O1_KLO + TM*PK*2)      // 73,728 B

__global__ void __launch_bounds__(256, 2)
qk_kernel(const float* __restrict__ q, const float* __restrict__ k,
          const float* __restrict__ mask, float* __restrict__ wts) {
    extern __shared__ __align__(16) char sm[];
    const uint32_t sb = s2u(sm);

    const int tid = threadIdx.x, w = tid >> 5, l = tid & 31;
    const int bh = blockIdx.x, qb = blockIdx.y, b = bh >> 4;   // HH=16

    const float* qp = q    + ((size_t)bh * SS + (size_t)qb * TM) * DD;
    const float* kp = k    + (size_t)bh * SS * DD;
    const float* mp = mask + ((size_t)b  * SS + (size_t)qb * TM) * SS;
    float*       wp = wts  + ((size_t)bh * SS + (size_t)qb * TM) * SS;

    // Load Q tile, split hi/lo (once)
    #pragma unroll
    for (int it = 0; it < 8; it++) {
        int lin = it * 256 + tid, row = lin >> 4, c4 = (lin & 15) << 2;
        float4 f = *(const float4*)(qp + (size_t)row * DD + c4);
        ull hp, lp; hilo4(f, hp, lp);
        *(ull*)(sm + O1_QHI + row * (PK*2) + c4 * 2) = hp;
        *(ull*)(sm + O1_QLO + row * (PK*2) + c4 * 2) = lp;
    }

    const int gq = l >> 2, qd = l & 3;
    const int row0 = w * 16 + gq, row1 = row0 + 8;
    // ldmatrix lane-address components
    const int a_r = l & 15, a_c = (l >> 4) * 8;                 // A (x4, row-major)
    const int b_r = l & 7, b_h = ((l >> 3) & 1) * 8, b_p = (l >> 4);  // B (x4, 2 n-tiles)

    float zrun0 = 0.f, zrun1 = 0.f;

    for (int t = 0; t < NT; t++) {
        __syncthreads();   // K smem reuse boundary
        #pragma unroll
        for (int it = 0; it < 8; it++) {
            int lin = it * 256 + tid, row = lin >> 4, c4 = (lin & 15) << 2;
            float4 f = *(const float4*)(kp + (size_t)(t * TN + row) * DD + c4);
            ull hp, lp; hilo4(f, hp, lp);
            *(ull*)(sm + O1_KHI + row * (PK*2) + c4 * 2) = hp;
            *(ull*)(sm + O1_KLO + row * (PK*2) + c4 * 2) = lp;
        }
        __syncthreads();

        float acc[16][4];
        #pragma unroll
        for (int i = 0; i < 16; i++)
            #pragma unroll
            for (int j = 0; j < 4; j++) acc[i][j] = 0.f;

        #pragma unroll
        for (int ks = 0; ks < 4; ks++) {
            uint32_t ah[4], al[4];
            uint32_t aaddr = sb + O1_QHI + ((w * 16 + a_r) * PK + ks * 16 + a_c) * 2;
            ldsm_x4(ah, aaddr);
            ldsm_x4(al, aaddr + (O1_QLO - O1_QHI));
            #pragma unroll
            for (int np = 0; np < 8; np++) {
                uint32_t bhr[4], blr[4];
                uint32_t baddr = sb + O1_KHI
                    + (((np * 2 + b_p) * 8 + b_r) * PK + ks * 16 + b_h) * 2;
                ldsm_x4(bhr, baddr);
                ldsm_x4(blr, baddr + (O1_KLO - O1_KHI));
                mma16816(acc[np*2+0], ah, bhr + 0);
                mma16816(acc[np*2+0], ah, blr + 0);
                mma16816(acc[np*2+0], al, bhr + 0);
                mma16816(acc[np*2+1], ah, bhr + 2);
                mma16816(acc[np*2+1], ah, blr + 2);
                mma16816(acc[np*2+1], al, bhr + 2);
            }
        }

        // Epilogue: mask + exp + store e, accumulate row sums
        float z0 = 0.f, z1 = 0.f;
        const float* m0p = mp + (size_t)row0 * SS + t * TN;
        const float* m1p = mp + (size_t)row1 * SS + t * TN;
        float* w0p = wp + (size_t)row0 * SS + t * TN;
        float* w1p = wp + (size_t)row1 * SS + t * TN;
        #pragma unroll
        for (int nt = 0; nt < 16; nt++) {
            int col = nt * 8 + qd * 2;
            float2 m0 = *(const float2*)(m0p + col);
            float2 m1 = *(const float2*)(m1p + col);
            float e00 = __expf(fmaf(m0.x, -1e9f, acc[nt][0] * SCL));
            float e01 = __expf(fmaf(m0.y, -1e9f, acc[nt][1] * SCL));
            float e10 = __expf(fmaf(m1.x, -1e9f, acc[nt][2] * SCL));
            float e11 = __expf(fmaf(m1.y, -1e9f, acc[nt][3] * SCL));
            *(float2*)(w0p + col) = make_float2(e00, e01);
            *(float2*)(w1p + col) = make_float2(e10, e11);
            z0 += e00 + e01;
            z1 += e10 + e11;
        }
        z0 += __shfl_xor_sync(0xffffffffu, z0, 1);
        z0 += __shfl_xor_sync(0xffffffffu, z0, 2);
        z1 += __shfl_xor_sync(0xffffffffu, z1, 1);
        z1 += __shfl_xor_sync(0xffffffffu, z1, 2);
        zrun0 += z0;
        zrun1 += z1;
    }

    if (qd == 0) {
        g_invZ[(size_t)bh * SS + (size_t)qb * TM + row0] = 1.0f / zrun0;
        g_invZ[(size_t)bh * SS + (size_t)qb * TM + row1] = 1.0f / zrun1;
    }
}

// ---------------------------------------------------------------------------
// Pass 2: normalize w in place; out = W @ V (bf16 3-term split, mma.sync).
// smem: Whi/Wlo [128][PW], Vhi/Vlo [128 j][PK] (row-major; V used via ldmatrix.trans)
// ---------------------------------------------------------------------------
#define O2_WHI 0
#define O2_WLO (O2_WHI + TM*PW*2)
#define O2_VHI (O2_WLO + TM*PW*2)
#define O2_VLO (O2_VHI + TN*PK*2)
#define O2_IZ  (O2_VLO + TN*PK*2)
#define SMEM2  (O2_IZ + TM*4)          // 107,008 B

__global__ void __launch_bounds__(256, 2)
pv_kernel(const float* __restrict__ v, float* __restrict__ wts,
          float* __restrict__ out) {
    extern __shared__ __align__(16) char sm[];
    const uint32_t sb = s2u(sm);

    const int tid = threadIdx.x, w = tid >> 5, l = tid & 31;
    const int bh = blockIdx.x, qb = blockIdx.y;

    const float* vp = v   + (size_t)bh * SS * DD;
    float*       wp = wts + ((size_t)bh * SS + (size_t)qb * TM) * SS;
    float*       op = out + ((size_t)bh * SS + (size_t)qb * TM) * DD;

    float* iZ = (float*)(sm + O2_IZ);
    if (tid < TM) iZ[tid] = g_invZ[(size_t)bh * SS + (size_t)qb * TM + tid];

    const int gq = l >> 2, qd = l & 3;
    const int a_r = l & 15, a_c = (l >> 4) * 8;                 // A (W) x4
    const int v_r = l & 7, v_j = ((l >> 3) & 1) * 8, v_p = (l >> 4);  // B (V) x4.trans

    float acc[8][4];
    #pragma unroll
    for (int i = 0; i < 8; i++)
        #pragma unroll
        for (int j = 0; j < 4; j++) acc[i][j] = 0.f;

    for (int t = 0; t < NT; t++) {
        __syncthreads();   // smem reuse boundary (also orders iZ on t==0)

        // W tile: read e, normalize, write back, split hi/lo to smem
        #pragma unroll
        for (int it = 0; it < 16; it++) {
            int lin = it * 256 + tid, row = lin >> 5, c4 = (lin & 31) << 2;
            float4 e = *(const float4*)(wp + (size_t)row * SS + t * TN + c4);
            float s = iZ[row];
            e.x *= s; e.y *= s; e.z *= s; e.w *= s;
            *(float4*)(wp + (size_t)row * SS + t * TN + c4) = e;
            ull hp, lp; hilo4(e, hp, lp);
            *(ull*)(sm + O2_WHI + row * (PW*2) + c4 * 2) = hp;
            *(ull*)(sm + O2_WLO + row * (PW*2) + c4 * 2) = lp;
        }
        // V tile [j][d], split hi/lo
        #pragma unroll
        for (int it = 0; it < 8; it++) {
            int lin = it * 256 + tid, j = lin >> 4, d4 = (lin & 15) << 2;
            float4 f = *(const float4*)(vp + (size_t)(t * TN + j) * DD + d4);
            ull hp, lp; hilo4(f, hp, lp);
            *(ull*)(sm + O2_VHI + j * (PK*2) + d4 * 2) = hp;
            *(ull*)(sm + O2_VLO + j * (PK*2) + d4 * 2) = lp;
        }
        __syncthreads();

        #pragma unroll
        for (int ks = 0; ks < 8; ks++) {
            uint32_t ah[4], al[4];
            uint32_t aaddr = sb + O2_WHI + ((w * 16 + a_r) * PW + ks * 16 + a_c) * 2;
            ldsm_x4(ah, aaddr);
            ldsm_x4(al, aaddr + (O2_WLO - O2_WHI));
            #pragma unroll
            for (int np = 0; np < 4; np++) {
                uint32_t bhr[4], blr[4];
                uint32_t baddr = sb + O2_VHI
                    + ((ks * 16 + v_j + v_r) * PK + (np * 2 + v_p) * 8) * 2;
                ldsm_x4t(bhr, baddr);
                ldsm_x4t(blr, baddr + (O2_VLO - O2_VHI));
                mma16816(acc[np*2+0], ah, bhr + 0);
                mma16816(acc[np*2+0], ah, blr + 0);
                mma16816(acc[np*2+0], al, bhr + 0);
                mma16816(acc[np*2+1], ah, bhr + 2);
                mma16816(acc[np*2+1], ah, blr + 2);
                mma16816(acc[np*2+1], al, bhr + 2);
            }
        }
    }

    // Epilogue: out[128][64]
    const int row0 = w * 16 + gq, row1 = row0 + 8;
    #pragma unroll
    for (int nt = 0; nt < 8; nt++) {
        int col = nt * 8 + qd * 2;
        *(float2*)(op + (size_t)row0 * DD + col) = make_float2(acc[nt][0], acc[nt][1]);
        *(float2*)(op + (size_t)row1 * DD + col) = make_float2(acc[nt][2], acc[nt][3]);
    }
}

// ---------------------------------------------------------------------------
extern "C" void kernel_launch(void* const* d_in, const int* in_sizes, int n_in,
                              void* d_out, int out_size) {
    (void)in_sizes; (void)n_in; (void)out_size;
    const float* q    = (const float*)d_in[0];
    const float* k    = (const float*)d_in[1];
    const float* v    = (const float*)d_in[2];
    const float* mask = (const float*)d_in[3];

    float* out = (float*)d_out;                        // [B,H,S,D]
    float* wts = out + (size_t)BB * HH * SS * DD;      // [B,H,S,S]

    cudaFuncSetAttribute(qk_kernel, cudaFuncAttributeMaxDynamicSharedMemorySize, SMEM1);
    cudaFuncSetAttribute(pv_kernel, cudaFuncAttributeMaxDynamicSharedMemorySize, SMEM2);

    dim3 grid(BHN, SS / TM);   // heads fastest -> per-batch mask slice stays L2-hot
    qk_kernel<<<grid, 256, SMEM1>>>(q, k, mask, wts);
    pv_kernel<<<grid, 256, SMEM2>>>(v, wts, out);
}